// round 11
// baseline (speedup 1.0000x reference)
#include <cuda_runtime.h>

#define BB 2
#define CC 256
#define MID 128
#define NN 6272
#define NT 49
#define SPLITS 3
#define PAD 130

// -------- static scratch (no runtime allocation allowed) --------
__device__ float g_Q[BB * MID * NN];
__device__ float g_K[BB * MID * NN];
__device__ float g_V[BB * MID * NN];
__device__ float g_Op[SPLITS * BB * NT * 128 * 128];   // partial O, [s][b][qt][q][m]
__device__ float g_ml[SPLITS * BB * NT * 256];          // per row: [0..127]=m, [128..255]=l

// -------- packed f32x2 helpers (PTX-only; ptxas never auto-fuses) --------
__device__ __forceinline__ unsigned long long pack2(float lo, float hi) {
    unsigned long long r;
    asm("mov.b64 %0, {%1, %2};" : "=l"(r) : "f"(lo), "f"(hi));
    return r;
}
__device__ __forceinline__ void unpack2(unsigned long long v, float& lo, float& hi) {
    asm("mov.b64 {%0, %1}, %2;" : "=f"(lo), "=f"(hi) : "l"(v));
}
__device__ __forceinline__ void fma2(unsigned long long& d, unsigned long long a, unsigned long long b) {
    asm("fma.rn.f32x2 %0, %1, %2, %0;" : "+l"(d) : "l"(a), "l"(b));
}
__device__ __forceinline__ void mul2(unsigned long long& d, unsigned long long a) {
    asm("mul.rn.f32x2 %0, %0, %1;" : "+l"(d) : "l"(a));
}
__device__ __forceinline__ unsigned long long lds2(const float* p) {
    return *reinterpret_cast<const unsigned long long*>(p);
}
__device__ __forceinline__ float ninf() { return __int_as_float(0xff800000); }

// ============================================================================
// Phase 1: QKV projection. out[b][m][n] = bias[m] + sum_c w[m][c]*x[b][c][n]
// grid (49 ntiles, 12 mchunks-of-32 over 384, B), block 64 (2 n per thread)
// ============================================================================
__global__ void __launch_bounds__(64) proj_kernel(
    const float* __restrict__ x,
    const float* __restrict__ w1, const float* __restrict__ b1,
    const float* __restrict__ w2, const float* __restrict__ b2,
    const float* __restrict__ w3, const float* __restrict__ b3)
{
    __shared__ float wsm[CC][34];  // [c][j], pad 34 keeps 8B alignment + low conflicts
    const int nt = blockIdx.x;
    const int mg = blockIdx.y;
    const int b  = blockIdx.z;
    const int t  = threadIdx.x;

    const int mbase  = (mg & 3) * 32;
    const int which  = mg >> 2;
    const float* w   = (which == 0) ? w1 : ((which == 1) ? w2 : w3);
    const float* bb  = (which == 0) ? b1 : ((which == 1) ? b2 : b3);
    float* out       = (which == 0) ? g_Q : ((which == 1) ? g_K : g_V);

    for (int idx = t; idx < 32 * CC; idx += 64) {
        int j = idx >> 8;
        int c = idx & 255;
        wsm[c][j] = w[(mbase + j) * CC + c];
    }
    __syncthreads();

    const int n0 = nt * 128 + 2 * t;
    const float* xp = x + (b * CC) * NN + n0;

    unsigned long long acc0[16], acc1[16];
#pragma unroll
    for (int j = 0; j < 16; ++j) { acc0[j] = 0ULL; acc1[j] = 0ULL; }

#pragma unroll 4
    for (int c = 0; c < CC; ++c) {
        float2 xv = *reinterpret_cast<const float2*>(xp + c * NN);
        unsigned long long xa = pack2(xv.x, xv.x);
        unsigned long long xb = pack2(xv.y, xv.y);
#pragma unroll
        for (int j = 0; j < 16; ++j) {
            unsigned long long wv = lds2(&wsm[c][2 * j]);
            fma2(acc0[j], xa, wv);
            fma2(acc1[j], xb, wv);
        }
    }

#pragma unroll
    for (int j = 0; j < 16; ++j) {
        float a0, a1, c0, c1;
        unpack2(acc0[j], a0, a1);
        unpack2(acc1[j], c0, c1);
        int m0 = mbase + 2 * j;
        float bv0 = bb[m0], bv1 = bb[m0 + 1];
        int base0 = (b * MID + m0) * NN + n0;
        int base1 = (b * MID + m0 + 1) * NN + n0;
        out[base0]     = a0 + bv0;
        out[base0 + 1] = c0 + bv0;
        out[base1]     = a1 + bv1;
        out[base1 + 1] = c1 + bv1;
    }
}

// ============================================================================
// Phase 2: flash attention, split-K=3. grid (NT, B, SPLITS), 256 threads.
// smem: Qs[m][q] | KPs (K[m][k] then P[k][q]) | Vs[k][m], all rows padded to 130.
// Thread (tq=t>>4, tk=t&15): q rows tq*8..+7 (paired for f32x2), k/m cols tk+16u.
// ============================================================================
__global__ void __launch_bounds__(256, 1) attn_kernel()
{
    extern __shared__ float sm[];
    float* Qs  = sm;
    float* KPs = sm + 128 * PAD;
    float* Vs  = sm + 2 * 128 * PAD;

    const int qt = blockIdx.x;
    const int b  = blockIdx.y;
    const int sp = blockIdx.z;
    const int t  = threadIdx.x;
    const int tq = t >> 4;
    const int tk = t & 15;
    const int q0 = qt * 128;

    const float* Qb = g_Q + b * MID * NN;
    const float* Kb = g_K + b * MID * NN;
    const float* Vb = g_V + b * MID * NN;

    // Q tile: Qs[m][q]
    for (int idx = t; idx < 128 * 128; idx += 256) {
        int m = idx >> 7, q = idx & 127;
        Qs[m * PAD + q] = Qb[m * NN + q0 + q];
    }

    unsigned long long o2[8][4];
#pragma unroll
    for (int u = 0; u < 8; ++u)
#pragma unroll
        for (int i2 = 0; i2 < 4; ++i2) o2[u][i2] = 0ULL;
    float mrow[8], lrow[8];
#pragma unroll
    for (int i = 0; i < 8; ++i) { mrow[i] = ninf(); lrow[i] = 0.f; }

    const int kt0 = sp * 16 + (sp > 0 ? 1 : 0);
    const int kt1 = kt0 + (sp == 0 ? 17 : 16);

    for (int kt = kt0; kt < kt1; ++kt) {
        __syncthreads();  // protect KPs/Vs from previous-iter readers
        const int k0g = kt * 128;
        for (int idx = t; idx < 128 * 128; idx += 256) {
            int m = idx >> 7, k = idx & 127;
            KPs[m * PAD + k] = Kb[m * NN + k0g + k];
        }
        for (int idx = t; idx < 128 * 128; idx += 256) {
            int m = idx >> 7, k = idx & 127;
            Vs[k * PAD + m] = Vb[m * NN + k0g + k];  // transpose to [k][m]
        }
        __syncthreads();

        // ---- S = Q @ K^T ----
        unsigned long long s2[8][4];
#pragma unroll
        for (int u = 0; u < 8; ++u)
#pragma unroll
            for (int i2 = 0; i2 < 4; ++i2) s2[u][i2] = 0ULL;

#pragma unroll 4
        for (int m = 0; m < 128; ++m) {
            unsigned long long q2[4];
#pragma unroll
            for (int i2 = 0; i2 < 4; ++i2)
                q2[i2] = lds2(&Qs[m * PAD + tq * 8 + 2 * i2]);
#pragma unroll
            for (int u = 0; u < 8; ++u) {
                float kv = KPs[m * PAD + tk + 16 * u];
                unsigned long long kv2 = pack2(kv, kv);
#pragma unroll
                for (int i2 = 0; i2 < 4; ++i2) fma2(s2[u][i2], q2[i2], kv2);
            }
        }

        // ---- online softmax (registers + 16-lane shuffles) ----
#pragma unroll
        for (int i2 = 0; i2 < 4; ++i2) {
            float a0 = ninf(), a1 = ninf();
#pragma unroll
            for (int u = 0; u < 8; ++u) {
                float vx, vy; unpack2(s2[u][i2], vx, vy);
                a0 = fmaxf(a0, vx); a1 = fmaxf(a1, vy);
            }
#pragma unroll
            for (int d = 1; d < 16; d <<= 1) {
                a0 = fmaxf(a0, __shfl_xor_sync(0xFFFFFFFFu, a0, d));
                a1 = fmaxf(a1, __shfl_xor_sync(0xFFFFFFFFu, a1, d));
            }
            const int r0 = 2 * i2, r1 = r0 + 1;
            float mn0 = fmaxf(mrow[r0], a0);
            float mn1 = fmaxf(mrow[r1], a1);
            float sc0 = __expf(mrow[r0] - mn0);
            float sc1 = __expf(mrow[r1] - mn1);
            mrow[r0] = mn0; mrow[r1] = mn1;
            float su0 = 0.f, su1 = 0.f;
#pragma unroll
            for (int u = 0; u < 8; ++u) {
                float vx, vy; unpack2(s2[u][i2], vx, vy);
                vx = __expf(vx - mn0);
                vy = __expf(vy - mn1);
                su0 += vx; su1 += vy;
                s2[u][i2] = pack2(vx, vy);
            }
#pragma unroll
            for (int d = 1; d < 16; d <<= 1) {
                su0 += __shfl_xor_sync(0xFFFFFFFFu, su0, d);
                su1 += __shfl_xor_sync(0xFFFFFFFFu, su1, d);
            }
            lrow[r0] = lrow[r0] * sc0 + su0;
            lrow[r1] = lrow[r1] * sc1 + su1;
            unsigned long long scp = pack2(sc0, sc1);
#pragma unroll
            for (int u = 0; u < 8; ++u) mul2(o2[u][i2], scp);
        }

        __syncthreads();  // everyone done reading Ks
        // P -> KPs as [k][q] (packed q-pair stores, 8B aligned since PAD even)
#pragma unroll
        for (int u = 0; u < 8; ++u) {
            int k = tk + 16 * u;
#pragma unroll
            for (int i2 = 0; i2 < 4; ++i2)
                *reinterpret_cast<unsigned long long*>(&KPs[k * PAD + tq * 8 + 2 * i2]) = s2[u][i2];
        }
        __syncthreads();

        // ---- O += P @ V ----
#pragma unroll 4
        for (int k = 0; k < 128; ++k) {
            unsigned long long p2[4];
#pragma unroll
            for (int i2 = 0; i2 < 4; ++i2)
                p2[i2] = lds2(&KPs[k * PAD + tq * 8 + 2 * i2]);
#pragma unroll
            for (int u = 0; u < 8; ++u) {
                float vv = Vs[k * PAD + tk + 16 * u];
                unsigned long long vv2 = pack2(vv, vv);
#pragma unroll
                for (int i2 = 0; i2 < 4; ++i2) fma2(o2[u][i2], p2[i2], vv2);
            }
        }
    }

    // ---- dump partial O (unnormalized) + (m, l) ----
    __syncthreads();
#pragma unroll
    for (int u = 0; u < 8; ++u) {
        int m = tk + 16 * u;
#pragma unroll
        for (int i2 = 0; i2 < 4; ++i2) {
            float vx, vy; unpack2(o2[u][i2], vx, vy);
            int q = tq * 8 + 2 * i2;
            KPs[q * 128 + m]       = vx;   // raw [q][m], reuse buffer
            KPs[(q + 1) * 128 + m] = vy;
        }
    }
    __syncthreads();
    const int obase = ((sp * BB + b) * NT + qt) << 14;
    for (int idx = t; idx < 128 * 128; idx += 256) g_Op[obase + idx] = KPs[idx];
    if (tk == 0) {
        const int mb = ((sp * BB + b) * NT + qt) * 256;
#pragma unroll
        for (int i = 0; i < 8; ++i) {
            g_ml[mb + tq * 8 + i]       = mrow[i];
            g_ml[mb + 128 + tq * 8 + i] = lrow[i];
        }
    }
}

// ============================================================================
// Phase 3: merge splits + w4 epilogue + bias + residual. grid (NT, B), 256 thr.
// smem: Os[m][q] pad 130 | w4s[m][c] pad 258 | ws[3][128] | invl[128]
// ============================================================================
#define OS_OFF   0
#define W4_OFF   (128 * 130)
#define WS_OFF   (W4_OFF + 128 * 258)
#define INVL_OFF (WS_OFF + 3 * 128)
#define COMB_FLOATS (INVL_OFF + 128)

__global__ void __launch_bounds__(256, 1) combine_kernel(
    const float* __restrict__ x, const float* __restrict__ w4,
    const float* __restrict__ b4, float* __restrict__ out)
{
    extern __shared__ float sm[];
    float* Os   = sm + OS_OFF;
    float* w4s  = sm + W4_OFF;
    float* ws   = sm + WS_OFF;
    float* invl = sm + INVL_OFF;

    const int qt = blockIdx.x;
    const int b  = blockIdx.y;
    const int t  = threadIdx.x;

    if (t < 128) {
        float m0 = ninf(); float msv[SPLITS], lsv[SPLITS];
#pragma unroll
        for (int s = 0; s < SPLITS; ++s) {
            const int mb = ((s * BB + b) * NT + qt) * 256;
            msv[s] = g_ml[mb + t];
            lsv[s] = g_ml[mb + 128 + t];
            m0 = fmaxf(m0, msv[s]);
        }
        float lsum = 0.f;
#pragma unroll
        for (int s = 0; s < SPLITS; ++s) {
            float w = __expf(msv[s] - m0);
            ws[s * 128 + t] = w;
            lsum += lsv[s] * w;
        }
        invl[t] = 1.f / lsum;
    }
    // w4s[m][c] (transpose of w4 [c][m])
    for (int idx = t; idx < CC * MID; idx += 256) {
        int c = idx >> 7, m = idx & 127;
        w4s[m * 258 + c] = w4[idx];
    }
    __syncthreads();

    // merge partials into Os[m][q], normalized
    for (int idx = t; idx < 128 * 128; idx += 256) {
        int q = idx >> 7, m = idx & 127;
        float a = 0.f;
#pragma unroll
        for (int s = 0; s < SPLITS; ++s) {
            const int ob = ((s * BB + b) * NT + qt) << 14;
            a += g_Op[ob + idx] * ws[s * 128 + q];
        }
        Os[m * PAD + q] = a * invl[q];
    }
    __syncthreads();

    // epilogue GEMM: e[c][q] = sum_m w4s[m][c] * Os[m][q]
    const int tc = t >> 4;   // 16 c-groups (16 c each, paired)
    const int tn = t & 15;   // lane side = q (coalesced out)
    unsigned long long e2[8][8];
#pragma unroll
    for (int v = 0; v < 8; ++v)
#pragma unroll
        for (int u = 0; u < 8; ++u) e2[v][u] = 0ULL;

#pragma unroll 4
    for (int m = 0; m < 128; ++m) {
        unsigned long long wv[8];
#pragma unroll
        for (int v = 0; v < 8; ++v)
            wv[v] = lds2(&w4s[m * 258 + tc * 16 + 2 * v]);
#pragma unroll
        for (int u = 0; u < 8; ++u) {
            float ov = Os[m * PAD + tn + 16 * u];
            unsigned long long ov2 = pack2(ov, ov);
#pragma unroll
            for (int v = 0; v < 8; ++v) fma2(e2[v][u], wv[v], ov2);
        }
    }

    const int n0 = qt * 128;
#pragma unroll
    for (int v = 0; v < 8; ++v) {
        int c = tc * 16 + 2 * v;
        float bv0 = b4[c], bv1 = b4[c + 1];
#pragma unroll
        for (int u = 0; u < 8; ++u) {
            float ex, ey; unpack2(e2[v][u], ex, ey);
            int q = tn + 16 * u;
            int i0 = (b * CC + c) * NN + n0 + q;
            int i1 = i0 + NN;
            out[i0] = x[i0] + bv0 + ex;
            out[i1] = x[i1] + bv1 + ey;
        }
    }
}

// ============================================================================
extern "C" void kernel_launch(void* const* d_in, const int* in_sizes, int n_in,
                              void* d_out, int out_size)
{
    (void)in_sizes; (void)n_in; (void)out_size;
    const float* x  = (const float*)d_in[0];
    const float* w1 = (const float*)d_in[1];
    const float* b1 = (const float*)d_in[2];
    const float* w2 = (const float*)d_in[3];
    const float* b2 = (const float*)d_in[4];
    const float* w3 = (const float*)d_in[5];
    const float* b3 = (const float*)d_in[6];
    const float* w4 = (const float*)d_in[7];
    const float* b4 = (const float*)d_in[8];
    float* out = (float*)d_out;

    const int attn_smem = 3 * 128 * PAD * (int)sizeof(float);     // 199,680 B
    const int comb_smem = COMB_FLOATS * (int)sizeof(float);       // 200,704 B
    cudaFuncSetAttribute(attn_kernel, cudaFuncAttributeMaxDynamicSharedMemorySize, attn_smem);
    cudaFuncSetAttribute(combine_kernel, cudaFuncAttributeMaxDynamicSharedMemorySize, comb_smem);

    proj_kernel<<<dim3(NT, 12, BB), 64>>>(x, w1, b1, w2, b2, w3, b3);
    attn_kernel<<<dim3(NT, BB, SPLITS), 256, attn_smem>>>();
    combine_kernel<<<dim3(NT, BB), 256, comb_smem>>>(x, w4, b4, out);
}

// round 12
// speedup vs baseline: 1.0025x; 1.0025x over previous
#include <cuda_runtime.h>

#define BB 2
#define CC 256
#define MID 128
#define NN 6272
#define NT 49
#define SPLITS 3
#define PAD 130

// -------- static scratch (no runtime allocation allowed) --------
__device__ float g_Q[BB * MID * NN];
__device__ float g_K[BB * MID * NN];
__device__ float g_V[BB * MID * NN];
__device__ float g_Op[SPLITS * BB * NT * 128 * 128];   // partial O, [s][b][qt][q][m]
__device__ float g_ml[SPLITS * BB * NT * 256];          // per row: [0..127]=m, [128..255]=l

// -------- packed f32x2 helpers (PTX-only; ptxas never auto-fuses) --------
__device__ __forceinline__ unsigned long long pack2(float lo, float hi) {
    unsigned long long r;
    asm("mov.b64 %0, {%1, %2};" : "=l"(r) : "f"(lo), "f"(hi));
    return r;
}
__device__ __forceinline__ void unpack2(unsigned long long v, float& lo, float& hi) {
    asm("mov.b64 {%0, %1}, %2;" : "=f"(lo), "=f"(hi) : "l"(v));
}
__device__ __forceinline__ void fma2(unsigned long long& d, unsigned long long a, unsigned long long b) {
    asm("fma.rn.f32x2 %0, %1, %2, %0;" : "+l"(d) : "l"(a), "l"(b));
}
__device__ __forceinline__ void mul2(unsigned long long& d, unsigned long long a) {
    asm("mul.rn.f32x2 %0, %0, %1;" : "+l"(d) : "l"(a));
}
__device__ __forceinline__ unsigned long long lds2(const float* p) {
    return *reinterpret_cast<const unsigned long long*>(p);
}
__device__ __forceinline__ float ninf() { return __int_as_float(0xff800000); }

// ============================================================================
// Phase 1: QKV projection. out[b][m][n] = bias[m] + sum_c w[m][c]*x[b][c][n]
// grid (49 ntiles, 12 mchunks-of-32 over 384, B), block 64 (2 n per thread)
// ============================================================================
__global__ void __launch_bounds__(64) proj_kernel(
    const float* __restrict__ x,
    const float* __restrict__ w1, const float* __restrict__ b1,
    const float* __restrict__ w2, const float* __restrict__ b2,
    const float* __restrict__ w3, const float* __restrict__ b3)
{
    __shared__ float wsm[CC][34];  // [c][j], pad 34 keeps 8B alignment + low conflicts
    const int nt = blockIdx.x;
    const int mg = blockIdx.y;
    const int b  = blockIdx.z;
    const int t  = threadIdx.x;

    const int mbase  = (mg & 3) * 32;
    const int which  = mg >> 2;
    const float* w   = (which == 0) ? w1 : ((which == 1) ? w2 : w3);
    const float* bb  = (which == 0) ? b1 : ((which == 1) ? b2 : b3);
    float* out       = (which == 0) ? g_Q : ((which == 1) ? g_K : g_V);

    for (int idx = t; idx < 32 * CC; idx += 64) {
        int j = idx >> 8;
        int c = idx & 255;
        wsm[c][j] = w[(mbase + j) * CC + c];
    }
    __syncthreads();

    const int n0 = nt * 128 + 2 * t;
    const float* xp = x + (b * CC) * NN + n0;

    unsigned long long acc0[16], acc1[16];
#pragma unroll
    for (int j = 0; j < 16; ++j) { acc0[j] = 0ULL; acc1[j] = 0ULL; }

#pragma unroll 4
    for (int c = 0; c < CC; ++c) {
        float2 xv = *reinterpret_cast<const float2*>(xp + c * NN);
        unsigned long long xa = pack2(xv.x, xv.x);
        unsigned long long xb = pack2(xv.y, xv.y);
#pragma unroll
        for (int j = 0; j < 16; ++j) {
            unsigned long long wv = lds2(&wsm[c][2 * j]);
            fma2(acc0[j], xa, wv);
            fma2(acc1[j], xb, wv);
        }
    }

#pragma unroll
    for (int j = 0; j < 16; ++j) {
        float a0, a1, c0, c1;
        unpack2(acc0[j], a0, a1);
        unpack2(acc1[j], c0, c1);
        int m0 = mbase + 2 * j;
        float bv0 = bb[m0], bv1 = bb[m0 + 1];
        int base0 = (b * MID + m0) * NN + n0;
        int base1 = (b * MID + m0 + 1) * NN + n0;
        out[base0]     = a0 + bv0;
        out[base0 + 1] = c0 + bv0;
        out[base1]     = a1 + bv1;
        out[base1 + 1] = c1 + bv1;
    }
}

// ============================================================================
// Phase 2: flash attention, split-K=3. grid (NT, B, SPLITS), 256 threads.
// smem: Qs[m][q] | KPs (K[m][k] then P[k][q]) | Vs[k][m], all rows padded to 130.
// Thread (tq=t>>4, tk=t&15): q rows tq*8..+7 (paired for f32x2), k/m cols tk+16u.
// ============================================================================
__global__ void __launch_bounds__(256, 1) attn_kernel()
{
    extern __shared__ float sm[];
    float* Qs  = sm;
    float* KPs = sm + 128 * PAD;
    float* Vs  = sm + 2 * 128 * PAD;

    const int qt = blockIdx.x;
    const int b  = blockIdx.y;
    const int sp = blockIdx.z;
    const int t  = threadIdx.x;
    const int tq = t >> 4;
    const int tk = t & 15;
    const int q0 = qt * 128;

    const float* Qb = g_Q + b * MID * NN;
    const float* Kb = g_K + b * MID * NN;
    const float* Vb = g_V + b * MID * NN;

    // Q tile: Qs[m][q]
    for (int idx = t; idx < 128 * 128; idx += 256) {
        int m = idx >> 7, q = idx & 127;
        Qs[m * PAD + q] = Qb[m * NN + q0 + q];
    }

    unsigned long long o2[8][4];
#pragma unroll
    for (int u = 0; u < 8; ++u)
#pragma unroll
        for (int i2 = 0; i2 < 4; ++i2) o2[u][i2] = 0ULL;
    float mrow[8], lrow[8];
#pragma unroll
    for (int i = 0; i < 8; ++i) { mrow[i] = ninf(); lrow[i] = 0.f; }

    const int kt0 = sp * 16 + (sp > 0 ? 1 : 0);
    const int kt1 = kt0 + (sp == 0 ? 17 : 16);

    for (int kt = kt0; kt < kt1; ++kt) {
        __syncthreads();  // protect KPs/Vs from previous-iter readers
        const int k0g = kt * 128;
        for (int idx = t; idx < 128 * 128; idx += 256) {
            int m = idx >> 7, k = idx & 127;
            KPs[m * PAD + k] = Kb[m * NN + k0g + k];
        }
        for (int idx = t; idx < 128 * 128; idx += 256) {
            int m = idx >> 7, k = idx & 127;
            Vs[k * PAD + m] = Vb[m * NN + k0g + k];  // transpose to [k][m]
        }
        __syncthreads();

        // ---- S = Q @ K^T ----
        unsigned long long s2[8][4];
#pragma unroll
        for (int u = 0; u < 8; ++u)
#pragma unroll
            for (int i2 = 0; i2 < 4; ++i2) s2[u][i2] = 0ULL;

#pragma unroll 4
        for (int m = 0; m < 128; ++m) {
            unsigned long long q2[4];
#pragma unroll
            for (int i2 = 0; i2 < 4; ++i2)
                q2[i2] = lds2(&Qs[m * PAD + tq * 8 + 2 * i2]);
#pragma unroll
            for (int u = 0; u < 8; ++u) {
                float kv = KPs[m * PAD + tk + 16 * u];
                unsigned long long kv2 = pack2(kv, kv);
#pragma unroll
                for (int i2 = 0; i2 < 4; ++i2) fma2(s2[u][i2], q2[i2], kv2);
            }
        }

        // ---- online softmax (registers + 16-lane shuffles) ----
#pragma unroll
        for (int i2 = 0; i2 < 4; ++i2) {
            float a0 = ninf(), a1 = ninf();
#pragma unroll
            for (int u = 0; u < 8; ++u) {
                float vx, vy; unpack2(s2[u][i2], vx, vy);
                a0 = fmaxf(a0, vx); a1 = fmaxf(a1, vy);
            }
#pragma unroll
            for (int d = 1; d < 16; d <<= 1) {
                a0 = fmaxf(a0, __shfl_xor_sync(0xFFFFFFFFu, a0, d));
                a1 = fmaxf(a1, __shfl_xor_sync(0xFFFFFFFFu, a1, d));
            }
            const int r0 = 2 * i2, r1 = r0 + 1;
            float mn0 = fmaxf(mrow[r0], a0);
            float mn1 = fmaxf(mrow[r1], a1);
            float sc0 = __expf(mrow[r0] - mn0);
            float sc1 = __expf(mrow[r1] - mn1);
            mrow[r0] = mn0; mrow[r1] = mn1;
            float su0 = 0.f, su1 = 0.f;
#pragma unroll
            for (int u = 0; u < 8; ++u) {
                float vx, vy; unpack2(s2[u][i2], vx, vy);
                vx = __expf(vx - mn0);
                vy = __expf(vy - mn1);
                su0 += vx; su1 += vy;
                s2[u][i2] = pack2(vx, vy);
            }
#pragma unroll
            for (int d = 1; d < 16; d <<= 1) {
                su0 += __shfl_xor_sync(0xFFFFFFFFu, su0, d);
                su1 += __shfl_xor_sync(0xFFFFFFFFu, su1, d);
            }
            lrow[r0] = lrow[r0] * sc0 + su0;
            lrow[r1] = lrow[r1] * sc1 + su1;
            unsigned long long scp = pack2(sc0, sc1);
#pragma unroll
            for (int u = 0; u < 8; ++u) mul2(o2[u][i2], scp);
        }

        __syncthreads();  // everyone done reading Ks
        // P -> KPs as [k][q] (packed q-pair stores, 8B aligned since PAD even)
#pragma unroll
        for (int u = 0; u < 8; ++u) {
            int k = tk + 16 * u;
#pragma unroll
            for (int i2 = 0; i2 < 4; ++i2)
                *reinterpret_cast<unsigned long long*>(&KPs[k * PAD + tq * 8 + 2 * i2]) = s2[u][i2];
        }
        __syncthreads();

        // ---- O += P @ V ----
#pragma unroll 4
        for (int k = 0; k < 128; ++k) {
            unsigned long long p2[4];
#pragma unroll
            for (int i2 = 0; i2 < 4; ++i2)
                p2[i2] = lds2(&KPs[k * PAD + tq * 8 + 2 * i2]);
#pragma unroll
            for (int u = 0; u < 8; ++u) {
                float vv = Vs[k * PAD + tk + 16 * u];
                unsigned long long vv2 = pack2(vv, vv);
#pragma unroll
                for (int i2 = 0; i2 < 4; ++i2) fma2(o2[u][i2], p2[i2], vv2);
            }
        }
    }

    // ---- dump partial O (unnormalized) + (m, l) ----
    __syncthreads();
#pragma unroll
    for (int u = 0; u < 8; ++u) {
        int m = tk + 16 * u;
#pragma unroll
        for (int i2 = 0; i2 < 4; ++i2) {
            float vx, vy; unpack2(o2[u][i2], vx, vy);
            int q = tq * 8 + 2 * i2;
            KPs[q * 128 + m]       = vx;   // raw [q][m], reuse buffer
            KPs[(q + 1) * 128 + m] = vy;
        }
    }
    __syncthreads();
    const int obase = ((sp * BB + b) * NT + qt) << 14;
    for (int idx = t; idx < 128 * 128; idx += 256) g_Op[obase + idx] = KPs[idx];
    if (tk == 0) {
        const int mb = ((sp * BB + b) * NT + qt) * 256;
#pragma unroll
        for (int i = 0; i < 8; ++i) {
            g_ml[mb + tq * 8 + i]       = mrow[i];
            g_ml[mb + 128 + tq * 8 + i] = lrow[i];
        }
    }
}

// ============================================================================
// Phase 3: merge splits + w4 epilogue + bias + residual. grid (NT, B), 256 thr.
// smem: Os[m][q] pad 130 | w4s[m][c] pad 258 | ws[3][128] | invl[128]
// ============================================================================
#define OS_OFF   0
#define W4_OFF   (128 * 130)
#define WS_OFF   (W4_OFF + 128 * 258)
#define INVL_OFF (WS_OFF + 3 * 128)
#define COMB_FLOATS (INVL_OFF + 128)

__global__ void __launch_bounds__(256, 1) combine_kernel(
    const float* __restrict__ x, const float* __restrict__ w4,
    const float* __restrict__ b4, float* __restrict__ out)
{
    extern __shared__ float sm[];
    float* Os   = sm + OS_OFF;
    float* w4s  = sm + W4_OFF;
    float* ws   = sm + WS_OFF;
    float* invl = sm + INVL_OFF;

    const int qt = blockIdx.x;
    const int b  = blockIdx.y;
    const int t  = threadIdx.x;

    if (t < 128) {
        float m0 = ninf(); float msv[SPLITS], lsv[SPLITS];
#pragma unroll
        for (int s = 0; s < SPLITS; ++s) {
            const int mb = ((s * BB + b) * NT + qt) * 256;
            msv[s] = g_ml[mb + t];
            lsv[s] = g_ml[mb + 128 + t];
            m0 = fmaxf(m0, msv[s]);
        }
        float lsum = 0.f;
#pragma unroll
        for (int s = 0; s < SPLITS; ++s) {
            float w = __expf(msv[s] - m0);
            ws[s * 128 + t] = w;
            lsum += lsv[s] * w;
        }
        invl[t] = 1.f / lsum;
    }
    // w4s[m][c] (transpose of w4 [c][m])
    for (int idx = t; idx < CC * MID; idx += 256) {
        int c = idx >> 7, m = idx & 127;
        w4s[m * 258 + c] = w4[idx];
    }
    __syncthreads();

    // merge partials into Os[m][q], normalized
    for (int idx = t; idx < 128 * 128; idx += 256) {
        int q = idx >> 7, m = idx & 127;
        float a = 0.f;
#pragma unroll
        for (int s = 0; s < SPLITS; ++s) {
            const int ob = ((s * BB + b) * NT + qt) << 14;
            a += g_Op[ob + idx] * ws[s * 128 + q];
        }
        Os[m * PAD + q] = a * invl[q];
    }
    __syncthreads();

    // epilogue GEMM: e[c][q] = sum_m w4s[m][c] * Os[m][q]
    const int tc = t >> 4;   // 16 c-groups (16 c each, paired)
    const int tn = t & 15;   // lane side = q (coalesced out)
    unsigned long long e2[8][8];
#pragma unroll
    for (int v = 0; v < 8; ++v)
#pragma unroll
        for (int u = 0; u < 8; ++u) e2[v][u] = 0ULL;

#pragma unroll 4
    for (int m = 0; m < 128; ++m) {
        unsigned long long wv[8];
#pragma unroll
        for (int v = 0; v < 8; ++v)
            wv[v] = lds2(&w4s[m * 258 + tc * 16 + 2 * v]);
#pragma unroll
        for (int u = 0; u < 8; ++u) {
            float ov = Os[m * PAD + tn + 16 * u];
            unsigned long long ov2 = pack2(ov, ov);
#pragma unroll
            for (int v = 0; v < 8; ++v) fma2(e2[v][u], wv[v], ov2);
        }
    }

    const int n0 = qt * 128;
#pragma unroll
    for (int v = 0; v < 8; ++v) {
        int c = tc * 16 + 2 * v;
        float bv0 = b4[c], bv1 = b4[c + 1];
#pragma unroll
        for (int u = 0; u < 8; ++u) {
            float ex, ey; unpack2(e2[v][u], ex, ey);
            int q = tn + 16 * u;
            int i0 = (b * CC + c) * NN + n0 + q;
            int i1 = i0 + NN;
            out[i0] = x[i0] + bv0 + ex;
            out[i1] = x[i1] + bv1 + ey;
        }
    }
}

// ============================================================================
extern "C" void kernel_launch(void* const* d_in, const int* in_sizes, int n_in,
                              void* d_out, int out_size)
{
    (void)in_sizes; (void)n_in; (void)out_size;
    const float* x  = (const float*)d_in[0];
    const float* w1 = (const float*)d_in[1];
    const float* b1 = (const float*)d_in[2];
    const float* w2 = (const float*)d_in[3];
    const float* b2 = (const float*)d_in[4];
    const float* w3 = (const float*)d_in[5];
    const float* b3 = (const float*)d_in[6];
    const float* w4 = (const float*)d_in[7];
    const float* b4 = (const float*)d_in[8];
    float* out = (float*)d_out;

    const int attn_smem = 3 * 128 * PAD * (int)sizeof(float);     // 199,680 B
    const int comb_smem = COMB_FLOATS * (int)sizeof(float);       // 200,704 B
    cudaFuncSetAttribute(attn_kernel, cudaFuncAttributeMaxDynamicSharedMemorySize, attn_smem);
    cudaFuncSetAttribute(combine_kernel, cudaFuncAttributeMaxDynamicSharedMemorySize, comb_smem);

    proj_kernel<<<dim3(NT, 12, BB), 64>>>(x, w1, b1, w2, b2, w3, b3);
    attn_kernel<<<dim3(NT, BB, SPLITS), 256, attn_smem>>>();
    combine_kernel<<<dim3(NT, BB), 256, comb_smem>>>(x, w4, b4, out);
}